// round 14
// baseline (speedup 1.0000x reference)
#include <cuda_runtime.h>
#include <math.h>

#define HV 3
#define NV 23
#define LV 35
#define NP 24
#define CVAL 64
#define BV 256
#define NN 529
// chunking: 4 l's per chunk, width 96, row stride 98, 9 chunks
#define ALC 4
#define AJ 96
#define AXP 98
#define ANCH 9

// ---- device scratch (static) ----
__device__ float g_M[HV * CVAL * CVAL];
__device__ float g_v1[HV * CVAL];
__device__ float g_v2[HV * CVAL];
__device__ float g_cc[HV];
__device__ float g_x2[BV * CVAL * LV * NP];      // [b][c][l][n24]
__device__ float g_xsum[BV * CVAL * NP];         // [b][c][n24] = sum_l x
__device__ float g_attraw[BV * HV * NN];
__device__ float g_scale[HV * NN];
__device__ float g_shift[HV * NN];
__device__ float g_A[BV * HV * NN];
__device__ float g_gcn2[BV * CVAL * LV * NP];    // [b][o][l][j24]

typedef unsigned long long ull;

__device__ __forceinline__ ull pk2(float v) {
    ull r; asm("mov.b64 %0, {%1, %1};" : "=l"(r) : "f"(v)); return r;
}
__device__ __forceinline__ void upk(ull p, float& lo, float& hi) {
    asm("mov.b64 {%0, %1}, %2;" : "=f"(lo), "=f"(hi) : "l"(p));
}
#define FMA2(acc, a, b) asm("fma.rn.f32x2 %0, %1, %2, %0;" : "+l"(acc) : "l"(a), "l"(b))

// per-thread chunk prefetch: thread t owns row c=t>>2, cols (t&3)*24..+24
__device__ __forceinline__ void prefetch_chunk(const float* __restrict__ xb, int ch,
                                               int tid, float4* pf) {
    int c = tid >> 2, p0 = (tid & 3) * 24;
    int base = ch * AJ + p0;
    const float* src = xb + c * (LV * NP) + base;
    #pragma unroll
    for (int u = 0; u < 6; u++) {
        int gp = base + 4 * u;
        if (gp + 3 < LV * NP) {
            pf[u] = *(const float4*)(src + 4 * u);
        } else {
            pf[u] = make_float4(0.f, 0.f, 0.f, 0.f);
        }
    }
}
__device__ __forceinline__ void commit_chunk(float* sx, int tid, const float4* pf) {
    int c = tid >> 2, p0 = (tid & 3) * 24;
    float* dst = sx + c * AXP + p0;
    #pragma unroll
    for (int u = 0; u < 6; u++) {
        *(float2*)(dst + 4 * u)     = make_float2(pf[u].x, pf[u].y);
        *(float2*)(dst + 4 * u + 2) = make_float2(pf[u].z, pf[u].w);
    }
}

// =====================================================================
// kX: transpose x[b,c,n,l] -> x2[b,c,l,n24]; also emit g_xsum row sums
// =====================================================================
__global__ void kX(const float* __restrict__ x) {
    __shared__ float s[8 * 805];
    int tid = threadIdx.x;
    size_t base = (size_t)blockIdx.x * (8 * 805);
    for (int i = tid; i < 8 * 805; i += 256) s[i] = x[base + i];
    __syncthreads();
    size_t obase = (size_t)blockIdx.x * (8 * 840);
    for (int i = tid; i < 8 * 840; i += 256) {
        int sl = i / 840, r = i - sl * 840, l = r / NP, n = r - l * NP;
        g_x2[obase + i] = (n < NV) ? s[sl * 805 + n * LV + l] : 0.f;
    }
    if (tid < 192) {
        int sl = tid / NP, n = tid - sl * NP;
        float sum = 0.f;
        if (n < NV) {
            const float* p = s + sl * 805 + n * LV;
            #pragma unroll 7
            for (int l = 0; l < LV; l++) sum += p[l];
        }
        g_xsum[(size_t)blockIdx.x * 192 + sl * NP + n] = sum;
    }
}

// =====================================================================
// kP: M_h = W2^T W1 (grid (3,8)); v1/v2/cc in part 0
// =====================================================================
__global__ void kP(const float* __restrict__ cw1, const float* __restrict__ cb1,
                   const float* __restrict__ cw2, const float* __restrict__ cb2) {
    int h = blockIdx.x, part = blockIdx.y, tid = threadIdx.x;
    __shared__ float sW1[4096], sW2[4096], sb1[64], sb2[64];
    for (int i = tid; i < 4096; i += 256) { sW1[i] = cw1[h * 4096 + i]; sW2[i] = cw2[h * 4096 + i]; }
    if (tid < 64) { sb1[tid] = cb1[h * 64 + tid]; sb2[tid] = cb2[h * 64 + tid]; }
    __syncthreads();
    #pragma unroll
    for (int q = 0; q < 2; q++) {
        int idx = part * 512 + q * 256 + tid;
        int c = idx >> 6, cp = idx & 63;
        float a = 0.f;
        #pragma unroll 8
        for (int o = 0; o < 64; o++) a = fmaf(sW2[o * 64 + c], sW1[o * 64 + cp], a);
        g_M[h * 4096 + idx] = a;
    }
    if (part == 0) {
        if (tid < 64) {
            float a1 = 0.f, a2 = 0.f;
            for (int o = 0; o < 64; o++) {
                a1 = fmaf(sb2[o], sW1[o * 64 + tid], a1);
                a2 = fmaf(sb1[o], sW2[o * 64 + tid], a2);
            }
            g_v1[h * 64 + tid] = a1; g_v2[h * 64 + tid] = a2;
        }
        if (tid == 0) {
            float a = 0.f;
            for (int o = 0; o < 64; o++) a = fmaf(sb1[o], sb2[o], a);
            g_cc[h] = (float)LV * a;
        }
    }
}

// =====================================================================
// kA: att_raw = (Gram(x, Mx) + t1[n] + t2[m] + cc)/2240
// grid (3,256), 256 thr, 66.8KB dyn smem, occ 3
// register-double-buffered chunk loads (prefetch hides LDG latency)
// =====================================================================
__global__ void __launch_bounds__(256, 3)
kA() {
    extern __shared__ float sm[];
    float* sM    = sm;              // 64*65 = 4160
    float* sx    = sM + 4160;       // 64*98 = 6272
    float* sy    = sx + 6272;       // 6272  -> 16704 floats total
    float* sgram = sM;              // alias (529)
    float* st1   = sM + 532;        // alias (24)
    float* st2   = sM + 556;        // alias (24)
    float* sxs   = sx;              // alias after last Gram (1536)
    int h = blockIdx.x, b = blockIdx.y, tid = threadIdx.x;

    const float* xb = g_x2 + (size_t)b * (CVAL * LV * NP);
    float4 pf[6];

    for (int i = tid; i < 4096; i += 256) sM[(i >> 6) * 65 + (i & 63)] = g_M[h * 4096 + i];
    prefetch_chunk(xb, 0, tid, pf);
    commit_chunk(sx, tid, pf);

    int tr = tid >> 4, tc = tid & 15;     // GEMM: 4 rows x 3 col-pairs
    int tile = tid >> 3, sl = tid & 7;    // Gram: 32 tiles, 8-way k-split
    int m0 = 3 * (tile >> 2), n0 = 6 * (tile & 3);

    ull gacc[3][3];
    #pragma unroll
    for (int i = 0; i < 3; i++)
        #pragma unroll
        for (int j = 0; j < 3; j++) gacc[i][j] = 0ull;

    __syncthreads();
    for (int ch = 0; ch < ANCH; ch++) {
        // prefetch next chunk (overlaps GEMM + Gram)
        if (ch + 1 < ANCH) prefetch_chunk(xb, ch + 1, tid, pf);
        // GEMM sy = M*sx (64 x 96, K=64), f32x2: 4 rows x 3 pairs
        {
            ull acc2[4][3];
            #pragma unroll
            for (int i = 0; i < 4; i++)
                #pragma unroll
                for (int j = 0; j < 3; j++) acc2[i][j] = 0ull;
            #pragma unroll 4
            for (int k = 0; k < 64; k++) {
                ull pa0 = pk2(sM[(tr * 4 + 0) * 65 + k]);
                ull pa1 = pk2(sM[(tr * 4 + 1) * 65 + k]);
                ull pa2 = pk2(sM[(tr * 4 + 2) * 65 + k]);
                ull pa3 = pk2(sM[(tr * 4 + 3) * 65 + k]);
                const ull* bp = (const ull*)(sx + k * AXP + 2 * tc);
                #pragma unroll
                for (int j = 0; j < 3; j++) {
                    ull bb = bp[16 * j];
                    FMA2(acc2[0][j], pa0, bb);
                    FMA2(acc2[1][j], pa1, bb);
                    FMA2(acc2[2][j], pa2, bb);
                    FMA2(acc2[3][j], pa3, bb);
                }
            }
            #pragma unroll
            for (int i = 0; i < 4; i++)
                #pragma unroll
                for (int j = 0; j < 3; j++)
                    *(ull*)(sy + (tr * 4 + i) * AXP + 2 * tc + 32 * j) = acc2[i][j];
        }
        __syncthreads();
        // Gram accumulate: 3m x 3 n-pairs, k-split over c
        for (int c = sl; c < 64; c += 8) {
            #pragma unroll
            for (int li = 0; li < ALC; li++) {
                int off = c * AXP + li * NP;
                ull pa0 = pk2(sx[off + m0]);
                ull pa1 = pk2(sx[off + m0 + 1]);
                ull pa2 = pk2(sx[off + m0 + 2]);
                const ull* bp = (const ull*)(sy + off + n0);
                ull b0 = bp[0], b1 = bp[1], b2 = bp[2];
                FMA2(gacc[0][0], pa0, b0); FMA2(gacc[0][1], pa0, b1); FMA2(gacc[0][2], pa0, b2);
                FMA2(gacc[1][0], pa1, b0); FMA2(gacc[1][1], pa1, b1); FMA2(gacc[1][2], pa1, b2);
                FMA2(gacc[2][0], pa2, b0); FMA2(gacc[2][1], pa2, b1); FMA2(gacc[2][2], pa2, b2);
            }
        }
        __syncthreads();   // Gram done reading sx/sy
        if (ch + 1 < ANCH) {
            commit_chunk(sx, tid, pf);
            __syncthreads();
        }
    }
    // epilogue (sM/sx aliases now safe: all reads completed at final sync)
    #pragma unroll
    for (int q = 0; q < 6; q++) {
        int i = tid + 256 * q;
        sxs[i] = g_xsum[(size_t)b * (CVAL * NP) + i];
    }
    #pragma unroll
    for (int i2 = 0; i2 < 3; i2++)
        #pragma unroll
        for (int p2 = 0; p2 < 3; p2++) {
            float lo, hi;
            upk(gacc[i2][p2], lo, hi);
            lo += __shfl_xor_sync(0xffffffffu, lo, 1);
            lo += __shfl_xor_sync(0xffffffffu, lo, 2);
            lo += __shfl_xor_sync(0xffffffffu, lo, 4);
            hi += __shfl_xor_sync(0xffffffffu, hi, 1);
            hi += __shfl_xor_sync(0xffffffffu, hi, 2);
            hi += __shfl_xor_sync(0xffffffffu, hi, 4);
            if (sl == 0) {
                int m = m0 + i2, n = n0 + 2 * p2;
                if (m < NV && n < NV) sgram[m * NV + n] = lo;
                if (m < NV && n + 1 < NV) sgram[m * NV + n + 1] = hi;
            }
        }
    __syncthreads();
    if (tid < NV) {
        float t = 0.f;
        for (int c = 0; c < 64; c++) t = fmaf(g_v1[h * 64 + c], sxs[c * NP + tid], t);
        st1[tid] = t;
    } else if (tid >= 32 && tid < 32 + NV) {
        int m = tid - 32;
        float t = 0.f;
        for (int c = 0; c < 64; c++) t = fmaf(g_v2[h * 64 + c], sxs[c * NP + m], t);
        st2[m] = t;
    }
    __syncthreads();
    float cc = g_cc[h];
    float* outp = g_attraw + (size_t)(b * HV + h) * NN;
    for (int p = tid; p < NN; p += 256) {
        int m = p / NV, n = p - m * NV;
        outp[p] = (sgram[p] + st1[n] + st2[m] + cc) * (1.f / 2240.f);
    }
}

// =====================================================================
// kB: BN batch stats, grid (3,17), 512 thr = 32 feat x 16 batch-groups
// =====================================================================
__global__ void kB(const float* __restrict__ gamma, const float* __restrict__ beta) {
    __shared__ double ds[512], ds2[512];
    int h = blockIdx.x;
    int fg = threadIdx.x & 31, bg = threadIdx.x >> 5;
    int f = blockIdx.y * 32 + fg;
    double s = 0.0, s2 = 0.0;
    if (f < NN) {
        for (int b = bg; b < BV; b += 16) {
            float v = g_attraw[(size_t)(b * HV + h) * NN + f];
            s += v; s2 += (double)v * v;
        }
    }
    ds[threadIdx.x] = s; ds2[threadIdx.x] = s2;
    __syncthreads();
    if (threadIdx.x < 32 && f < NN) {
        double ts = 0.0, ts2 = 0.0;
        #pragma unroll
        for (int g = 0; g < 16; g++) { ts += ds[fg + 32 * g]; ts2 += ds2[fg + 32 * g]; }
        double mean = ts * (1.0 / BV);
        double var = ts2 * (1.0 / BV) - mean * mean;
        float sc = gamma[h * NN + f] / sqrtf((float)var + 1e-5f);
        g_scale[h * NN + f] = sc;
        g_shift[h * NN + f] = beta[h * NN + f] - (float)mean * sc;
    }
}

// =====================================================================
// kC: affine + column softmax + A assembly
// =====================================================================
__global__ void kC(const float* __restrict__ A_ske, const float* __restrict__ att) {
    __shared__ float sz[NN], cs[NV];
    int h = blockIdx.x, b = blockIdx.y, tid = threadIdx.x;
    const float* raw = g_attraw + (size_t)(b * HV + h) * NN;
    for (int p = tid; p < NN; p += 256)
        sz[p] = fmaf(raw[p], g_scale[h * NN + p], g_shift[h * NN + p]);
    __syncthreads();
    if (tid < NV) {
        int n = tid;
        float mx = -1e30f;
        for (int m = 0; m < NV; m++) mx = fmaxf(mx, sz[m * NV + n]);
        float s = 0.f;
        for (int m = 0; m < NV; m++) { float e = expf(sz[m * NV + n] - mx); sz[m * NV + n] = e; s += e; }
        cs[n] = s;
    }
    __syncthreads();
    float* outp = g_A + (size_t)(b * HV + h) * NN;
    for (int p = tid; p < NN; p += 256) {
        int n = p % NV;
        outp[p] = A_ske[h * NN + p] + att[h * NN + p] + sz[p] / cs[n];
    }
}

// =====================================================================
// kG: per-head: supp = x*A_h, acc += W_h^T supp; f32x2
// grid (256,9), 256 thr, 73.5KB dyn smem, occ 3
// W prefetch for head h+1 overlaps head h compute
// =====================================================================
__global__ void __launch_bounds__(256, 3)
kG(const float* __restrict__ mw, const float* __restrict__ mb) {
    extern __shared__ float sm[];
    float* sx   = sm;               // 6272
    float* ssup = sx + 6272;        // 6272
    float* sW   = ssup + 6272;      // 64*65 = 4160
    float* sA2  = sW + 4160;        // 3*23*24 = 1656 (+8) -> 18368 floats
    int b = blockIdx.x, ch = blockIdx.y, tid = threadIdx.x;
    const float* xb = g_x2 + (size_t)b * (CVAL * LV * NP);

    for (int i = tid; i < HV * NV * NP; i += 256) {
        int h = i / (NV * NP), r = i - h * (NV * NP), ii = r / NP, j = r - ii * NP;
        sA2[i] = (j < NV) ? g_A[(size_t)b * (HV * NN) + h * NN + ii * NV + j] : 0.f;
    }
    {
        float4 pf[6];
        prefetch_chunk(xb, ch, tid, pf);
        commit_chunk(sx, tid, pf);
    }
    // head 0 weights direct
    for (int i = tid; i < 4096; i += 256) {
        int o = i >> 6, c = i & 63;
        sW[c * 65 + o] = mw[i];
    }

    int tr = tid >> 4, tc = tid & 15;
    ull acc2[4][3];
    #pragma unroll
    for (int i = 0; i < 4; i++) {
        int o = tr * 4 + i;
        ull mbs = pk2(mb[o] + mb[64 + o] + mb[128 + o]);
        #pragma unroll
        for (int j = 0; j < 3; j++) acc2[i][j] = mbs;
    }

    int sc = tid & 63, j0 = (tid >> 6) * 6;   // supp slot: c, 6-col group
    float4 pfw[4];
    __syncthreads();

    for (int h = 0; h < HV; h++) {
        // prefetch next head's weights (overlaps supp + head GEMM)
        if (h + 1 < HV) {
            const float4* src = (const float4*)(mw + (h + 1) * 4096 + 16 * tid);
            #pragma unroll
            for (int u = 0; u < 4; u++) pfw[u] = src[u];
        }
        // supp: each thread computes row sc, cols [li*24+j0, +6) for all 4 li
        {
            ull a2[4][3];
            #pragma unroll
            for (int li = 0; li < 4; li++)
                #pragma unroll
                for (int j = 0; j < 3; j++) a2[li][j] = 0ull;
            const float* Ab = sA2 + h * (NV * NP) + j0;
            const float* xr = sx + sc * AXP;
            for (int i2 = 0; i2 < NV; i2++) {
                const ull* Ar = (const ull*)(Ab + i2 * NP);
                ull b0 = Ar[0], b1 = Ar[1], b2 = Ar[2];
                #pragma unroll
                for (int li = 0; li < 4; li++) {
                    ull pv = pk2(xr[li * NP + i2]);
                    FMA2(a2[li][0], pv, b0);
                    FMA2(a2[li][1], pv, b1);
                    FMA2(a2[li][2], pv, b2);
                }
            }
            #pragma unroll
            for (int li = 0; li < 4; li++) {
                ull* dst = (ull*)(ssup + sc * AXP + li * NP + j0);
                dst[0] = a2[li][0]; dst[1] = a2[li][1]; dst[2] = a2[li][2];
            }
        }
        __syncthreads();   // ssup visible; sW(h) stable
        // head GEMM accumulate: K=64, 4 rows x 3 pairs
        #pragma unroll 4
        for (int k = 0; k < 64; k++) {
            ull pa0 = pk2(sW[k * 65 + tr * 4 + 0]);
            ull pa1 = pk2(sW[k * 65 + tr * 4 + 1]);
            ull pa2 = pk2(sW[k * 65 + tr * 4 + 2]);
            ull pa3 = pk2(sW[k * 65 + tr * 4 + 3]);
            const ull* bp = (const ull*)(ssup + k * AXP + 2 * tc);
            #pragma unroll
            for (int j = 0; j < 3; j++) {
                ull bb = bp[16 * j];
                FMA2(acc2[0][j], pa0, bb);
                FMA2(acc2[1][j], pa1, bb);
                FMA2(acc2[2][j], pa2, bb);
                FMA2(acc2[3][j], pa3, bb);
            }
        }
        if (h + 1 < HV) {
            __syncthreads();   // GEMM done: sW free for commit, ssup free for next supp
            const float* pw = (const float*)pfw;
            #pragma unroll
            for (int u = 0; u < 16; u++) {
                int idx = 16 * tid + u;
                sW[(idx & 63) * 65 + (idx >> 6)] = pw[u];
            }
        }
    }
    // store gcn2 as 64-bit pairs
    #pragma unroll
    for (int jp = 0; jp < 3; jp++) {
        int col = 2 * tc + 32 * jp;
        int li = col / NP, j = col - li * NP;
        int l = ch * ALC + li;
        if (l < LV) {
            #pragma unroll
            for (int i = 0; i < 4; i++) {
                int o = tr * 4 + i;
                *(ull*)&g_gcn2[((size_t)(b * 64 + o) * LV + l) * NP + j] = acc2[i][jp];
            }
        }
    }
}

// =====================================================================
// kT: out[(b,o,j), l'] = sum_l gcn2[(b,o),l,j]*w[l,l'] + bias[l']
// =====================================================================
__global__ void kT(const float* __restrict__ wseq, const float* __restrict__ bias,
                   float* __restrict__ out) {
    extern __shared__ float smT[];
    float* sg = smT;              // 8*840 = 6720
    float* sw = sg + 6720;        // 35*36 = 1260
    float* sb = sw + 1260;        // 40
    float* so = sb + 40;          // 8*805 = 6440 -> 14460 floats
    int tid = threadIdx.x;
    size_t gbase = (size_t)blockIdx.x * (8 * LV * NP);
    for (int i = tid; i < 8 * LV * NP; i += 256) sg[i] = g_gcn2[gbase + i];
    for (int i = tid; i < LV * LV; i += 256) sw[(i / LV) * 36 + (i % LV)] = wseq[i];
    if (tid < LV) sb[tid] = bias[tid];
    __syncthreads();
    if (tid < 240) {
        int pair = tid / 30, r = tid - pair * 30, jg = r / 5, lg = r - jg * 5;
        int j0 = jg * 4, lp0 = lg * 7;
        float a[4][7];
        #pragma unroll
        for (int t = 0; t < 4; t++)
            #pragma unroll
            for (int u = 0; u < 7; u++) a[t][u] = sb[lp0 + u];
        const float* gp = sg + pair * (LV * NP) + j0;
        #pragma unroll 5
        for (int l = 0; l < LV; l++) {
            float g0 = gp[l * NP + 0], g1 = gp[l * NP + 1], g2 = gp[l * NP + 2], g3 = gp[l * NP + 3];
            const float* wr = sw + l * 36 + lp0;
            #pragma unroll
            for (int u = 0; u < 7; u++) {
                float w = wr[u];
                a[0][u] = fmaf(g0, w, a[0][u]);
                a[1][u] = fmaf(g1, w, a[1][u]);
                a[2][u] = fmaf(g2, w, a[2][u]);
                a[3][u] = fmaf(g3, w, a[3][u]);
            }
        }
        #pragma unroll
        for (int t = 0; t < 4; t++) {
            int jj = j0 + t;
            if (jj < NV) {
                #pragma unroll
                for (int u = 0; u < 7; u++)
                    so[pair * 805 + jj * LV + lp0 + u] = a[t][u];
            }
        }
    }
    __syncthreads();
    size_t obase = (size_t)blockIdx.x * (8 * 805);
    for (int i = tid; i < 8 * 805; i += 256) out[obase + i] = so[i];
}

extern "C" void kernel_launch(void* const* d_in, const int* in_sizes, int n_in,
                              void* d_out, int out_size) {
    const float* x     = (const float*)d_in[0];
    const float* cw1   = (const float*)d_in[1];
    const float* cb1   = (const float*)d_in[2];
    const float* cw2   = (const float*)d_in[3];
    const float* cb2   = (const float*)d_in[4];
    const float* gamma = (const float*)d_in[5];
    const float* beta  = (const float*)d_in[6];
    const float* mw    = (const float*)d_in[7];
    const float* mb    = (const float*)d_in[8];
    const float* att   = (const float*)d_in[9];
    const float* A_ske = (const float*)d_in[10];
    const float* wseq  = (const float*)d_in[11];
    const float* bias  = (const float*)d_in[12];
    float* out = (float*)d_out;

    static bool attr_done = false;
    if (!attr_done) {
        cudaFuncSetAttribute(kA, cudaFuncAttributeMaxDynamicSharedMemorySize, 16704 * 4);
        cudaFuncSetAttribute(kG, cudaFuncAttributeMaxDynamicSharedMemorySize, 18368 * 4);
        cudaFuncSetAttribute(kT, cudaFuncAttributeMaxDynamicSharedMemorySize, 14460 * 4);
        attr_done = true;
    }

    kX<<<2048, 256>>>(x);
    kP<<<dim3(HV, 8), 256>>>(cw1, cb1, cw2, cb2);
    kA<<<dim3(HV, BV), 256, 16704 * 4>>>();
    kB<<<dim3(HV, 17), 512>>>(gamma, beta);
    kC<<<dim3(HV, BV), 256>>>(A_ske, att);
    kG<<<dim3(BV, ANCH), 256, 18368 * 4>>>(mw, mb);
    kT<<<2048, 256, 14460 * 4>>>(wseq, bias, out);
}

// round 15
// speedup vs baseline: 1.0762x; 1.0762x over previous
#include <cuda_runtime.h>
#include <math.h>

#define HV 3
#define NV 23
#define LV 35
#define NP 24
#define CVAL 64
#define BV 256
#define NN 529
// chunking: 4 l's per chunk, width 96, row stride 98, 9 chunks
#define ALC 4
#define AJ 96
#define AXP 98
#define ANCH 9

// ---- device scratch (static) ----
__device__ float g_M[HV * CVAL * CVAL];
__device__ float g_v1[HV * CVAL];
__device__ float g_v2[HV * CVAL];
__device__ float g_cc[HV];
__device__ float g_x2[BV * CVAL * LV * NP];      // [b][c][l][n24]
__device__ float g_xsum[BV * CVAL * NP];         // [b][c][n24] = sum_l x
__device__ float g_attp[4][BV * HV * NN];        // quarter partials of att_raw
__device__ float g_attraw[BV * HV * NN];
__device__ float g_scale[HV * NN];
__device__ float g_shift[HV * NN];
__device__ float g_A[BV * HV * NN];
__device__ float g_gcn2[BV * CVAL * LV * NP];    // [b][o][l][j24]

typedef unsigned long long ull;

__device__ __forceinline__ ull pk2(float v) {
    ull r; asm("mov.b64 %0, {%1, %1};" : "=l"(r) : "f"(v)); return r;
}
__device__ __forceinline__ void upk(ull p, float& lo, float& hi) {
    asm("mov.b64 {%0, %1}, %2;" : "=f"(lo), "=f"(hi) : "l"(p));
}
#define FMA2(acc, a, b) asm("fma.rn.f32x2 %0, %1, %2, %0;" : "+l"(acc) : "l"(a), "l"(b))

// =====================================================================
// kX: transpose x[b,c,n,l] -> x2[b,c,l,n24]; also emit g_xsum row sums
// =====================================================================
__global__ void kX(const float* __restrict__ x) {
    __shared__ float s[8 * 805];
    int tid = threadIdx.x;
    size_t base = (size_t)blockIdx.x * (8 * 805);
    for (int i = tid; i < 8 * 805; i += 256) s[i] = x[base + i];
    __syncthreads();
    size_t obase = (size_t)blockIdx.x * (8 * 840);
    for (int i = tid; i < 8 * 840; i += 256) {
        int sl = i / 840, r = i - sl * 840, l = r / NP, n = r - l * NP;
        g_x2[obase + i] = (n < NV) ? s[sl * 805 + n * LV + l] : 0.f;
    }
    if (tid < 192) {
        int sl = tid / NP, n = tid - sl * NP;
        float sum = 0.f;
        if (n < NV) {
            const float* p = s + sl * 805 + n * LV;
            #pragma unroll 7
            for (int l = 0; l < LV; l++) sum += p[l];
        }
        g_xsum[(size_t)blockIdx.x * 192 + sl * NP + n] = sum;
    }
}

// =====================================================================
// kP: M_h = W2^T W1 (grid (3,8)); v1/v2/cc in part 0
// =====================================================================
__global__ void kP(const float* __restrict__ cw1, const float* __restrict__ cb1,
                   const float* __restrict__ cw2, const float* __restrict__ cb2) {
    int h = blockIdx.x, part = blockIdx.y, tid = threadIdx.x;
    __shared__ float sW1[4096], sW2[4096], sb1[64], sb2[64];
    for (int i = tid; i < 4096; i += 256) { sW1[i] = cw1[h * 4096 + i]; sW2[i] = cw2[h * 4096 + i]; }
    if (tid < 64) { sb1[tid] = cb1[h * 64 + tid]; sb2[tid] = cb2[h * 64 + tid]; }
    __syncthreads();
    #pragma unroll
    for (int q = 0; q < 2; q++) {
        int idx = part * 512 + q * 256 + tid;
        int c = idx >> 6, cp = idx & 63;
        float a = 0.f;
        #pragma unroll 8
        for (int o = 0; o < 64; o++) a = fmaf(sW2[o * 64 + c], sW1[o * 64 + cp], a);
        g_M[h * 4096 + idx] = a;
    }
    if (part == 0) {
        if (tid < 64) {
            float a1 = 0.f, a2 = 0.f;
            for (int o = 0; o < 64; o++) {
                a1 = fmaf(sb2[o], sW1[o * 64 + tid], a1);
                a2 = fmaf(sb1[o], sW2[o * 64 + tid], a2);
            }
            g_v1[h * 64 + tid] = a1; g_v2[h * 64 + tid] = a2;
        }
        if (tid == 0) {
            float a = 0.f;
            for (int o = 0; o < 64; o++) a = fmaf(sb1[o], sb2[o], a);
            g_cc[h] = (float)LV * a;
        }
    }
}

// =====================================================================
// kA: quarter-split partial Gram. grid (3,256,4), 256 thr, 66.8KB, occ 3
// quarter q does chunks {0-2 | 3-4 | 5-6 | 7-8}; q0 adds t1/t2/cc terms
// =====================================================================
__global__ void __launch_bounds__(256, 3)
kA() {
    extern __shared__ float sm[];
    float* sM    = sm;              // 64*65 = 4160
    float* sx    = sM + 4160;       // 64*98 = 6272
    float* sy    = sx + 6272;       // 6272  -> 16704 floats total
    float* sgram = sM;              // alias (529)
    float* st1   = sM + 532;        // alias (24)
    float* st2   = sM + 556;        // alias (24)
    float* sxs   = sx;              // alias after last Gram (1536)
    int h = blockIdx.x, b = blockIdx.y, q = blockIdx.z, tid = threadIdx.x;
    int ch0 = (q == 0) ? 0 : (2 * q + 1);
    int chend = ch0 + ((q == 0) ? 3 : 2);

    for (int i = tid; i < 4096; i += 256) sM[(i >> 6) * 65 + (i & 63)] = g_M[h * 4096 + i];

    int tr = tid >> 4, tc = tid & 15;     // GEMM: 4 rows x 3 col-pairs
    int tile = tid >> 3, sl = tid & 7;    // Gram: 32 tiles, 8-way k-split
    int m0 = 3 * (tile >> 2), n0 = 6 * (tile & 3);
    const float* xb = g_x2 + (size_t)b * (CVAL * LV * NP);

    ull gacc[3][3];
    #pragma unroll
    for (int i = 0; i < 3; i++)
        #pragma unroll
        for (int j = 0; j < 3; j++) gacc[i][j] = 0ull;

    for (int ch = ch0; ch < chend; ch++) {
        int l0p = ch * AJ;
        __syncthreads();
        // coalesced chunk load; zero-fill beyond l=35
        for (int i = tid; i < CVAL * AJ; i += 256) {
            int c = i / AJ, p = i - c * AJ;
            int gp = l0p + p;
            sx[c * AXP + p] = (gp < LV * NP) ? xb[c * (LV * NP) + gp] : 0.f;
        }
        __syncthreads();
        // GEMM sy = M*sx (64 x 96, K=64), f32x2: 4 rows x 3 pairs
        {
            ull acc2[4][3];
            #pragma unroll
            for (int i = 0; i < 4; i++)
                #pragma unroll
                for (int j = 0; j < 3; j++) acc2[i][j] = 0ull;
            #pragma unroll 4
            for (int k = 0; k < 64; k++) {
                ull pa0 = pk2(sM[(tr * 4 + 0) * 65 + k]);
                ull pa1 = pk2(sM[(tr * 4 + 1) * 65 + k]);
                ull pa2 = pk2(sM[(tr * 4 + 2) * 65 + k]);
                ull pa3 = pk2(sM[(tr * 4 + 3) * 65 + k]);
                const ull* bp = (const ull*)(sx + k * AXP + 2 * tc);
                #pragma unroll
                for (int j = 0; j < 3; j++) {
                    ull bb = bp[16 * j];
                    FMA2(acc2[0][j], pa0, bb);
                    FMA2(acc2[1][j], pa1, bb);
                    FMA2(acc2[2][j], pa2, bb);
                    FMA2(acc2[3][j], pa3, bb);
                }
            }
            #pragma unroll
            for (int i = 0; i < 4; i++)
                #pragma unroll
                for (int j = 0; j < 3; j++)
                    *(ull*)(sy + (tr * 4 + i) * AXP + 2 * tc + 32 * j) = acc2[i][j];
        }
        __syncthreads();
        // Gram accumulate: 3m x 3 n-pairs, k-split over c
        for (int c = sl; c < 64; c += 8) {
            #pragma unroll
            for (int li = 0; li < ALC; li++) {
                int off = c * AXP + li * NP;
                ull pa0 = pk2(sx[off + m0]);
                ull pa1 = pk2(sx[off + m0 + 1]);
                ull pa2 = pk2(sx[off + m0 + 2]);
                const ull* bp = (const ull*)(sy + off + n0);
                ull b0 = bp[0], b1 = bp[1], b2 = bp[2];
                FMA2(gacc[0][0], pa0, b0); FMA2(gacc[0][1], pa0, b1); FMA2(gacc[0][2], pa0, b2);
                FMA2(gacc[1][0], pa1, b0); FMA2(gacc[1][1], pa1, b1); FMA2(gacc[1][2], pa1, b2);
                FMA2(gacc[2][0], pa2, b0); FMA2(gacc[2][1], pa2, b1); FMA2(gacc[2][2], pa2, b2);
            }
        }
    }
    __syncthreads();   // all Gram reads done; sM/sx aliases writable
    if (q == 0) {
        // stage xsum from global into sx alias
        #pragma unroll
        for (int qq = 0; qq < 6; qq++) {
            int i = tid + 256 * qq;
            sxs[i] = g_xsum[(size_t)b * (CVAL * NP) + i];
        }
    }
    // unpack + shuffle-reduce k-split; write into sgram (aliases sM)
    #pragma unroll
    for (int i2 = 0; i2 < 3; i2++)
        #pragma unroll
        for (int p2 = 0; p2 < 3; p2++) {
            float lo, hi;
            upk(gacc[i2][p2], lo, hi);
            lo += __shfl_xor_sync(0xffffffffu, lo, 1);
            lo += __shfl_xor_sync(0xffffffffu, lo, 2);
            lo += __shfl_xor_sync(0xffffffffu, lo, 4);
            hi += __shfl_xor_sync(0xffffffffu, hi, 1);
            hi += __shfl_xor_sync(0xffffffffu, hi, 2);
            hi += __shfl_xor_sync(0xffffffffu, hi, 4);
            if (sl == 0) {
                int m = m0 + i2, n = n0 + 2 * p2;
                if (m < NV && n < NV) sgram[m * NV + n] = lo;
                if (m < NV && n + 1 < NV) sgram[m * NV + n + 1] = hi;
            }
        }
    __syncthreads();
    if (q == 0) {
        if (tid < NV) {
            float t = 0.f;
            for (int c = 0; c < 64; c++) t = fmaf(g_v1[h * 64 + c], sxs[c * NP + tid], t);
            st1[tid] = t;
        } else if (tid >= 32 && tid < 32 + NV) {
            int m = tid - 32;
            float t = 0.f;
            for (int c = 0; c < 64; c++) t = fmaf(g_v2[h * 64 + c], sxs[c * NP + m], t);
            st2[m] = t;
        }
    }
    __syncthreads();
    float* outp = g_attp[q] + (size_t)(b * HV + h) * NN;
    if (q == 0) {
        float cc = g_cc[h];
        for (int p = tid; p < NN; p += 256) {
            int m = p / NV, n = p - m * NV;
            outp[p] = (sgram[p] + st1[n] + st2[m] + cc) * (1.f / 2240.f);
        }
    } else {
        for (int p = tid; p < NN; p += 256)
            outp[p] = sgram[p] * (1.f / 2240.f);
    }
}

// =====================================================================
// kB: sum quarter partials -> g_attraw; BN batch stats -> affine
// grid (3,17), 512 thr = 32 feat x 16 batch-groups
// =====================================================================
__global__ void kB(const float* __restrict__ gamma, const float* __restrict__ beta) {
    __shared__ double ds[512], ds2[512];
    int h = blockIdx.x;
    int fg = threadIdx.x & 31, bg = threadIdx.x >> 5;
    int f = blockIdx.y * 32 + fg;
    double s = 0.0, s2 = 0.0;
    if (f < NN) {
        for (int b = bg; b < BV; b += 16) {
            size_t idx = (size_t)(b * HV + h) * NN + f;
            float v = g_attp[0][idx] + g_attp[1][idx] + g_attp[2][idx] + g_attp[3][idx];
            g_attraw[idx] = v;
            s += v; s2 += (double)v * v;
        }
    }
    ds[threadIdx.x] = s; ds2[threadIdx.x] = s2;
    __syncthreads();
    if (threadIdx.x < 32 && f < NN) {
        double ts = 0.0, ts2 = 0.0;
        #pragma unroll
        for (int g = 0; g < 16; g++) { ts += ds[fg + 32 * g]; ts2 += ds2[fg + 32 * g]; }
        double mean = ts * (1.0 / BV);
        double var = ts2 * (1.0 / BV) - mean * mean;
        float sc = gamma[h * NN + f] / sqrtf((float)var + 1e-5f);
        g_scale[h * NN + f] = sc;
        g_shift[h * NN + f] = beta[h * NN + f] - (float)mean * sc;
    }
}

// =====================================================================
// kC: affine + column softmax + A assembly
// =====================================================================
__global__ void kC(const float* __restrict__ A_ske, const float* __restrict__ att) {
    __shared__ float sz[NN], cs[NV];
    int h = blockIdx.x, b = blockIdx.y, tid = threadIdx.x;
    const float* raw = g_attraw + (size_t)(b * HV + h) * NN;
    for (int p = tid; p < NN; p += 256)
        sz[p] = fmaf(raw[p], g_scale[h * NN + p], g_shift[h * NN + p]);
    __syncthreads();
    if (tid < NV) {
        int n = tid;
        float mx = -1e30f;
        for (int m = 0; m < NV; m++) mx = fmaxf(mx, sz[m * NV + n]);
        float s = 0.f;
        for (int m = 0; m < NV; m++) { float e = expf(sz[m * NV + n] - mx); sz[m * NV + n] = e; s += e; }
        cs[n] = s;
    }
    __syncthreads();
    float* outp = g_A + (size_t)(b * HV + h) * NN;
    for (int p = tid; p < NN; p += 256) {
        int n = p % NV;
        outp[p] = A_ske[h * NN + p] + att[h * NN + p] + sz[p] / cs[n];
    }
}

// =====================================================================
// kG: per-head: supp = x*A_h, acc += W_h^T supp; f32x2 (R13 form)
// grid (256,9), 256 thr, 73.5KB dyn smem, occ 3
// =====================================================================
__global__ void __launch_bounds__(256, 3)
kG(const float* __restrict__ mw, const float* __restrict__ mb) {
    extern __shared__ float sm[];
    float* sx   = sm;               // 6272
    float* ssup = sx + 6272;        // 6272
    float* sW   = ssup + 6272;      // 64*65 = 4160
    float* sA2  = sW + 4160;        // 3*23*24 = 1656 (+8) -> 18368 floats
    int b = blockIdx.x, ch = blockIdx.y, tid = threadIdx.x;
    int l0p = ch * AJ;
    const float* xb = g_x2 + (size_t)b * (CVAL * LV * NP);

    for (int i = tid; i < HV * NV * NP; i += 256) {
        int h = i / (NV * NP), r = i - h * (NV * NP), ii = r / NP, j = r - ii * NP;
        sA2[i] = (j < NV) ? g_A[(size_t)b * (HV * NN) + h * NN + ii * NV + j] : 0.f;
    }
    for (int i = tid; i < CVAL * AJ; i += 256) {
        int c = i / AJ, p = i - c * AJ;
        int gp = l0p + p;
        sx[c * AXP + p] = (gp < LV * NP) ? xb[c * (LV * NP) + gp] : 0.f;
    }

    int tr = tid >> 4, tc = tid & 15;
    ull acc2[4][3];
    #pragma unroll
    for (int i = 0; i < 4; i++) {
        int o = tr * 4 + i;
        ull mbs = pk2(mb[o] + mb[64 + o] + mb[128 + o]);
        #pragma unroll
        for (int j = 0; j < 3; j++) acc2[i][j] = mbs;
    }

    int sc = tid & 63, j0 = (tid >> 6) * 6;   // supp slot: c, 6-col group

    for (int h = 0; h < HV; h++) {
        __syncthreads();
        for (int i = tid; i < 4096; i += 256) {
            int o = i >> 6, c = i & 63;
            sW[c * 65 + o] = mw[h * 4096 + i];
        }
        // supp: each thread computes row sc, cols [li*24+j0, +6) for all 4 li
        {
            ull a2[4][3];
            #pragma unroll
            for (int li = 0; li < 4; li++)
                #pragma unroll
                for (int j = 0; j < 3; j++) a2[li][j] = 0ull;
            const float* Ab = sA2 + h * (NV * NP) + j0;
            const float* xr = sx + sc * AXP;
            for (int i2 = 0; i2 < NV; i2++) {
                const ull* Ar = (const ull*)(Ab + i2 * NP);
                ull b0 = Ar[0], b1 = Ar[1], b2 = Ar[2];
                #pragma unroll
                for (int li = 0; li < 4; li++) {
                    ull pv = pk2(xr[li * NP + i2]);
                    FMA2(a2[li][0], pv, b0);
                    FMA2(a2[li][1], pv, b1);
                    FMA2(a2[li][2], pv, b2);
                }
            }
            #pragma unroll
            for (int li = 0; li < 4; li++) {
                ull* dst = (ull*)(ssup + sc * AXP + li * NP + j0);
                dst[0] = a2[li][0]; dst[1] = a2[li][1]; dst[2] = a2[li][2];
            }
        }
        __syncthreads();
        // head GEMM accumulate: K=64, 4 rows x 3 pairs
        #pragma unroll 4
        for (int k = 0; k < 64; k++) {
            ull pa0 = pk2(sW[k * 65 + tr * 4 + 0]);
            ull pa1 = pk2(sW[k * 65 + tr * 4 + 1]);
            ull pa2 = pk2(sW[k * 65 + tr * 4 + 2]);
            ull pa3 = pk2(sW[k * 65 + tr * 4 + 3]);
            const ull* bp = (const ull*)(ssup + k * AXP + 2 * tc);
            #pragma unroll
            for (int j = 0; j < 3; j++) {
                ull bb = bp[16 * j];
                FMA2(acc2[0][j], pa0, bb);
                FMA2(acc2[1][j], pa1, bb);
                FMA2(acc2[2][j], pa2, bb);
                FMA2(acc2[3][j], pa3, bb);
            }
        }
    }
    // store gcn2 as 64-bit pairs
    #pragma unroll
    for (int jp = 0; jp < 3; jp++) {
        int col = 2 * tc + 32 * jp;
        int li = col / NP, j = col - li * NP;
        int l = ch * ALC + li;
        if (l < LV) {
            #pragma unroll
            for (int i = 0; i < 4; i++) {
                int o = tr * 4 + i;
                *(ull*)&g_gcn2[((size_t)(b * 64 + o) * LV + l) * NP + j] = acc2[i][jp];
            }
        }
    }
}

// =====================================================================
// kT: out[(b,o,j), l'] = sum_l gcn2[(b,o),l,j]*w[l,l'] + bias[l']
// =====================================================================
__global__ void kT(const float* __restrict__ wseq, const float* __restrict__ bias,
                   float* __restrict__ out) {
    extern __shared__ float smT[];
    float* sg = smT;              // 8*840 = 6720
    float* sw = sg + 6720;        // 35*36 = 1260
    float* sb = sw + 1260;        // 40
    float* so = sb + 40;          // 8*805 = 6440 -> 14460 floats
    int tid = threadIdx.x;
    size_t gbase = (size_t)blockIdx.x * (8 * LV * NP);
    for (int i = tid; i < 8 * LV * NP; i += 256) sg[i] = g_gcn2[gbase + i];
    for (int i = tid; i < LV * LV; i += 256) sw[(i / LV) * 36 + (i % LV)] = wseq[i];
    if (tid < LV) sb[tid] = bias[tid];
    __syncthreads();
    if (tid < 240) {
        int pair = tid / 30, r = tid - pair * 30, jg = r / 5, lg = r - jg * 5;
        int j0 = jg * 4, lp0 = lg * 7;
        float a[4][7];
        #pragma unroll
        for (int t = 0; t < 4; t++)
            #pragma unroll
            for (int u = 0; u < 7; u++) a[t][u] = sb[lp0 + u];
        const float* gp = sg + pair * (LV * NP) + j0;
        #pragma unroll 5
        for (int l = 0; l < LV; l++) {
            float g0 = gp[l * NP + 0], g1 = gp[l * NP + 1], g2 = gp[l * NP + 2], g3 = gp[l * NP + 3];
            const float* wr = sw + l * 36 + lp0;
            #pragma unroll
            for (int u = 0; u < 7; u++) {
                float w = wr[u];
                a[0][u] = fmaf(g0, w, a[0][u]);
                a[1][u] = fmaf(g1, w, a[1][u]);
                a[2][u] = fmaf(g2, w, a[2][u]);
                a[3][u] = fmaf(g3, w, a[3][u]);
            }
        }
        #pragma unroll
        for (int t = 0; t < 4; t++) {
            int jj = j0 + t;
            if (jj < NV) {
                #pragma unroll
                for (int u = 0; u < 7; u++)
                    so[pair * 805 + jj * LV + lp0 + u] = a[t][u];
            }
        }
    }
    __syncthreads();
    size_t obase = (size_t)blockIdx.x * (8 * 805);
    for (int i = tid; i < 8 * 805; i += 256) out[obase + i] = so[i];
}

extern "C" void kernel_launch(void* const* d_in, const int* in_sizes, int n_in,
                              void* d_out, int out_size) {
    const float* x     = (const float*)d_in[0];
    const float* cw1   = (const float*)d_in[1];
    const float* cb1   = (const float*)d_in[2];
    const float* cw2   = (const float*)d_in[3];
    const float* cb2   = (const float*)d_in[4];
    const float* gamma = (const float*)d_in[5];
    const float* beta  = (const float*)d_in[6];
    const float* mw    = (const float*)d_in[7];
    const float* mb    = (const float*)d_in[8];
    const float* att   = (const float*)d_in[9];
    const float* A_ske = (const float*)d_in[10];
    const float* wseq  = (const float*)d_in[11];
    const float* bias  = (const float*)d_in[12];
    float* out = (float*)d_out;

    static bool attr_done = false;
    if (!attr_done) {
        cudaFuncSetAttribute(kA, cudaFuncAttributeMaxDynamicSharedMemorySize, 16704 * 4);
        cudaFuncSetAttribute(kG, cudaFuncAttributeMaxDynamicSharedMemorySize, 18368 * 4);
        cudaFuncSetAttribute(kT, cudaFuncAttributeMaxDynamicSharedMemorySize, 14460 * 4);
        attr_done = true;
    }

    kX<<<2048, 256>>>(x);
    kP<<<dim3(HV, 8), 256>>>(cw1, cb1, cw2, cb2);
    kA<<<dim3(HV, BV, 4), 256, 16704 * 4>>>();
    kB<<<dim3(HV, 17), 512>>>(gamma, beta);
    kC<<<dim3(HV, BV), 256>>>(A_ske, att);
    kG<<<dim3(BV, ANCH), 256, 18368 * 4>>>(mw, mb);
    kT<<<2048, 256, 14460 * 4>>>(wseq, bias, out);
}